// round 6
// baseline (speedup 1.0000x reference)
#include <cuda_runtime.h>
#include <math.h>
#include <stdint.h>

#define IN_DIM 1024
#define ED 256
#define NE 512
#define NTOK_MAX 131072
#define TT 32
#define PDP 68
#define XDP 132
#define BK1 32
#define BK2 8

typedef unsigned long long u64;
typedef uint32_t u32;

__device__ __align__(16) float g_WT[IN_DIM * ED];     // W transposed [k][n]
__device__ __align__(16) float g_cnT[ED * NE];        // normalized centers [k][e]
__device__ __align__(16) float g_P[(size_t)NTOK_MAX * ED];
__device__ float g_sq[NTOK_MAX];

static __device__ __forceinline__ u64 pack2(float lo, float hi) {
    u64 r; asm("mov.b64 %0, {%1, %2};" : "=l"(r) : "f"(lo), "f"(hi)); return r;
}
static __device__ __forceinline__ void unpack2(u64 v, float& lo, float& hi) {
    asm("mov.b64 {%0, %1}, %2;" : "=f"(lo), "=f"(hi) : "l"(v));
}
static __device__ __forceinline__ void ffma2(u64& d, u64 a, u64 b) {
    asm("fma.rn.f32x2 %0, %1, %2, %0;" : "+l"(d) : "l"(a), "l"(b));
}
static __device__ __forceinline__ void fadd2(u64& d, u64 a) {
    asm("add.rn.f32x2 %0, %0, %1;" : "+l"(d) : "l"(a));
}

// ---- bulk async copy + mbarrier helpers ----
static __device__ __forceinline__ void mbar_init(u32 mbar, u32 cnt) {
    asm volatile("mbarrier.init.shared.b64 [%0], %1;" :: "r"(mbar), "r"(cnt) : "memory");
}
static __device__ __forceinline__ void mbar_expect_tx(u32 mbar, u32 bytes) {
    asm volatile("mbarrier.arrive.expect_tx.shared.b64 _, [%0], %1;" :: "r"(mbar), "r"(bytes) : "memory");
}
static __device__ __forceinline__ void bulk_g2s(u32 dst, const float* src,
                                                u32 bytes, u32 mbar) {
    asm volatile("cp.async.bulk.shared::cta.global.mbarrier::complete_tx::bytes [%0], [%1], %2, [%3];"
                 :: "r"(dst), "l"(src), "r"(bytes), "r"(mbar) : "memory");
}
static __device__ __forceinline__ void mbar_wait(u32 mbar, u32 parity) {
    u32 done;
    asm volatile(
        "{\n\t.reg .pred p;\n\t"
        "mbarrier.try_wait.parity.acquire.cta.shared::cta.b64 p, [%1], %2;\n\t"
        "selp.b32 %0, 1, 0, p;\n\t}"
        : "=r"(done) : "r"(mbar), "r"(parity) : "memory");
    if (!done) {
        asm volatile(
            "{\n\t.reg .pred P1;\n\t"
            "WL_%=:\n\t"
            "mbarrier.try_wait.parity.acquire.cta.shared::cta.b64 P1, [%0], %1, 0x989680;\n\t"
            "@P1 bra.uni WD_%=;\n\t"
            "bra.uni WL_%=;\n\t"
            "WD_%=:\n\t}"
            :: "r"(mbar), "r"(parity) : "memory");
    }
}

static __device__ __forceinline__ void upd(float v, int i,
                                           float& v1, int& i1, float& v2, int& i2) {
    if (v > v1 || (v == v1 && i < i1)) { v2 = v1; i2 = i1; v1 = v; i1 = i; }
    else if (v > v2 || (v == v2 && i < i2)) { v2 = v; i2 = i; }
}

// ---------------- prep: normalize centers -> g_cnT [k][e] ----------------
__global__ void cnorm_kernel(const float* __restrict__ centers) {
    __shared__ float ws[8];
    int e = blockIdx.x, t = threadIdx.x;
    float v = centers[e * ED + t];
    float s = v * v;
    #pragma unroll
    for (int o = 16; o; o >>= 1) s += __shfl_xor_sync(0xffffffffu, s, o);
    if ((t & 31) == 0) ws[t >> 5] = s;
    __syncthreads();
    float tot = 0.f;
    #pragma unroll
    for (int i = 0; i < 8; ++i) tot += ws[i];
    float norm = fmaxf(sqrtf(tot), 1e-12f);
    g_cnT[t * NE + e] = v / norm;
}

// ---------------- prep: transpose W [n][k] -> g_WT [k][n] ----------------
__global__ void prep_wt_kernel(const float* __restrict__ W) {
    __shared__ float t[32][33];
    int bx = blockIdx.x * 32;
    int by = blockIdx.y * 32;
    int x = threadIdx.x, y = threadIdx.y;
    #pragma unroll
    for (int j = 0; j < 32; j += 8)
        t[y + j][x] = W[(size_t)(by + y + j) * IN_DIM + bx + x];
    __syncthreads();
    #pragma unroll
    for (int j = 0; j < 32; j += 8)
        g_WT[(size_t)(bx + y + j) * ED + by + x] = t[x][y + j];
}

// ---------------- K1: P = x @ W^T + b  (BK=32, bulk W tiles) ----------------
#define W1BYTES (BK1 * ED * 4)

__global__ __launch_bounds__(256, 2)
void k1_kernel(const float* __restrict__ x, const float* __restrict__ bias) {
    extern __shared__ __align__(16) float sm1[];
    float* xd = sm1;                       // [2][BK1][XDP]  duplicated x, k-major
    float* wS = sm1 + 2 * BK1 * XDP;       // [2][BK1][ED]   W tile, k-major
    __shared__ __align__(8) u64 mbars[2];

    const int tid = threadIdx.x;
    const int w = tid >> 5, lane = tid & 31;
    const int t0 = blockIdx.x * 64;
    const int mb = w * 8;
    const int nA = lane * 4, nB = 128 + lane * 4;

    const int xr = tid >> 2, xk = (tid & 3) * 8;
    const float* xp = x + (size_t)(t0 + xr) * IN_DIM + xk;

    u32 wS_u32 = (u32)__cvta_generic_to_shared(wS);
    u32 mb0 = (u32)__cvta_generic_to_shared(&mbars[0]);
    u32 mb1 = mb0 + 8;
    int ph0 = 0, ph1 = 0;

    u64 acc[8][4];
    #pragma unroll
    for (int m = 0; m < 8; ++m)
        #pragma unroll
        for (int p = 0; p < 4; ++p) acc[m][p] = 0ull;

    if (tid == 0) { mbar_init(mb0, 1); mbar_init(mb1, 1); }
    __syncthreads();

    if (tid == 0) { mbar_expect_tx(mb0, W1BYTES); bulk_g2s(wS_u32, g_WT, W1BYTES, mb0); }
    float4 xs0 = *(const float4*)xp;
    float4 xs1 = *(const float4*)(xp + 4);
    {
        float v[8] = {xs0.x, xs0.y, xs0.z, xs0.w, xs1.x, xs1.y, xs1.z, xs1.w};
        #pragma unroll
        for (int i = 0; i < 8; ++i)
            *(float2*)(xd + (xk + i) * XDP + 2 * xr) = make_float2(v[i], v[i]);
    }
    mbar_wait(mb0, ph0); ph0 ^= 1;
    __syncthreads();

    const int NT = IN_DIM / BK1;
    for (int kt = 0; kt < NT; ++kt) {
        const int buf = kt & 1;
        const float* xb = xd + buf * (BK1 * XDP);
        const float* wb = wS + buf * (BK1 * ED);
        if (kt + 1 < NT) {
            if (tid == 0) {
                u32 m = buf ? mb0 : mb1;
                mbar_expect_tx(m, W1BYTES);
                bulk_g2s(wS_u32 + (u32)((buf ^ 1) * W1BYTES),
                         g_WT + (size_t)(kt + 1) * BK1 * ED, W1BYTES, m);
            }
            xs0 = *(const float4*)(xp + (kt + 1) * BK1);
            xs1 = *(const float4*)(xp + (kt + 1) * BK1 + 4);
        }
        #pragma unroll
        for (int k = 0; k < BK1; ++k) {
            ulonglong2 qa0 = *(const ulonglong2*)(xb + k * XDP + 2 * mb + 0);
            ulonglong2 qa1 = *(const ulonglong2*)(xb + k * XDP + 2 * mb + 4);
            ulonglong2 qa2 = *(const ulonglong2*)(xb + k * XDP + 2 * mb + 8);
            ulonglong2 qa3 = *(const ulonglong2*)(xb + k * XDP + 2 * mb + 12);
            ulonglong2 qb0 = *(const ulonglong2*)(wb + k * ED + nA);
            ulonglong2 qb1 = *(const ulonglong2*)(wb + k * ED + nB);
            u64 B0 = qb0.x, B1 = qb0.y, B2 = qb1.x, B3 = qb1.y;
            ffma2(acc[0][0], qa0.x, B0); ffma2(acc[0][1], qa0.x, B1);
            ffma2(acc[0][2], qa0.x, B2); ffma2(acc[0][3], qa0.x, B3);
            ffma2(acc[1][0], qa0.y, B0); ffma2(acc[1][1], qa0.y, B1);
            ffma2(acc[1][2], qa0.y, B2); ffma2(acc[1][3], qa0.y, B3);
            ffma2(acc[2][0], qa1.x, B0); ffma2(acc[2][1], qa1.x, B1);
            ffma2(acc[2][2], qa1.x, B2); ffma2(acc[2][3], qa1.x, B3);
            ffma2(acc[3][0], qa1.y, B0); ffma2(acc[3][1], qa1.y, B1);
            ffma2(acc[3][2], qa1.y, B2); ffma2(acc[3][3], qa1.y, B3);
            ffma2(acc[4][0], qa2.x, B0); ffma2(acc[4][1], qa2.x, B1);
            ffma2(acc[4][2], qa2.x, B2); ffma2(acc[4][3], qa2.x, B3);
            ffma2(acc[5][0], qa2.y, B0); ffma2(acc[5][1], qa2.y, B1);
            ffma2(acc[5][2], qa2.y, B2); ffma2(acc[5][3], qa2.y, B3);
            ffma2(acc[6][0], qa3.x, B0); ffma2(acc[6][1], qa3.x, B1);
            ffma2(acc[6][2], qa3.x, B2); ffma2(acc[6][3], qa3.x, B3);
            ffma2(acc[7][0], qa3.y, B0); ffma2(acc[7][1], qa3.y, B1);
            ffma2(acc[7][2], qa3.y, B2); ffma2(acc[7][3], qa3.y, B3);
        }
        if (kt + 1 < NT) {
            float* xn = xd + (buf ^ 1) * (BK1 * XDP);
            float v[8] = {xs0.x, xs0.y, xs0.z, xs0.w, xs1.x, xs1.y, xs1.z, xs1.w};
            #pragma unroll
            for (int i = 0; i < 8; ++i)
                *(float2*)(xn + (xk + i) * XDP + 2 * xr) = make_float2(v[i], v[i]);
            if (buf) { mbar_wait(mb0, ph0); ph0 ^= 1; }
            else     { mbar_wait(mb1, ph1); ph1 ^= 1; }
        }
        __syncthreads();
    }

    // epilogue: +bias (packed), sumsq butterfly, store P rows + g_sq
    u64 bp0 = *(const u64*)(bias + nA);
    u64 bp1 = *(const u64*)(bias + nA + 2);
    u64 bp2 = *(const u64*)(bias + nB);
    u64 bp3 = *(const u64*)(bias + nB + 2);
    #pragma unroll
    for (int m = 0; m < 8; ++m) {
        fadd2(acc[m][0], bp0); fadd2(acc[m][1], bp1);
        fadd2(acc[m][2], bp2); fadd2(acc[m][3], bp3);
        u64 sp = 0ull;
        ffma2(sp, acc[m][0], acc[m][0]); ffma2(sp, acc[m][1], acc[m][1]);
        ffma2(sp, acc[m][2], acc[m][2]); ffma2(sp, acc[m][3], acc[m][3]);
        float lo, hi; unpack2(sp, lo, hi);
        float s = lo + hi;
        #pragma unroll
        for (int o = 16; o; o >>= 1) s += __shfl_xor_sync(0xffffffffu, s, o);
        int row = t0 + mb + m;
        u64* pr = (u64*)(g_P + (size_t)row * ED);
        pr[nA / 2]     = acc[m][0];
        pr[nA / 2 + 1] = acc[m][1];
        pr[nB / 2]     = acc[m][2];
        pr[nB / 2 + 1] = acc[m][3];
        if (lane == 0) g_sq[row] = s;
    }
}

// ---------------- K2: sims + top-2 + softmax (dup-P, MOV-free inner loop) ----------------
#define C2BYTES (BK2 * NE * 4)

__global__ __launch_bounds__(256, 2)
void k2_kernel(float* __restrict__ out, int ntok) {
    extern __shared__ __align__(16) float sm2[];
    float* Pd = sm2;                       // [ED][PDP] : P transposed+duplicated [k][2m]
    float* ct = sm2 + ED * PDP;            // [2][BK2][NE] center tiles
    __shared__ __align__(8) u64 mbars[2];

    const int tid = threadIdx.x;
    const int w = tid >> 5, lane = tid & 31;
    const int t0 = blockIdx.x * TT;
    const int mb = (w >> 1) * 8;           // 8 tokens per warp-pair
    const int nh = (w & 1) * 256;          // expert half
    const int nA = nh + lane * 4, nB = nh + 128 + lane * 4;

    u32 ct_u32 = (u32)__cvta_generic_to_shared(ct);
    u32 mb0 = (u32)__cvta_generic_to_shared(&mbars[0]);
    u32 mb1 = mb0 + 8;
    int ph0 = 0, ph1 = 0;

    if (tid == 0) { mbar_init(mb0, 1); mbar_init(mb1, 1); }
    __syncthreads();
    if (tid == 0) { mbar_expect_tx(mb0, C2BYTES); bulk_g2s(ct_u32, g_cnT, C2BYTES, mb0); }

    // transpose P tile into Pd with duplication (overlaps with bulk copy)
    const int pr = tid >> 3, pcq = (tid & 7) * 4;
    #pragma unroll
    for (int j = 0; j < 8; ++j) {
        int c = pcq + 32 * j;
        float4 v = *(const float4*)(g_P + (size_t)(t0 + pr) * ED + c);
        *(float2*)(Pd + (c + 0) * PDP + 2 * pr) = make_float2(v.x, v.x);
        *(float2*)(Pd + (c + 1) * PDP + 2 * pr) = make_float2(v.y, v.y);
        *(float2*)(Pd + (c + 2) * PDP + 2 * pr) = make_float2(v.z, v.z);
        *(float2*)(Pd + (c + 3) * PDP + 2 * pr) = make_float2(v.w, v.w);
    }
    mbar_wait(mb0, ph0); ph0 ^= 1;
    __syncthreads();

    u64 acc[8][4];
    #pragma unroll
    for (int m = 0; m < 8; ++m)
        #pragma unroll
        for (int p = 0; p < 4; ++p) acc[m][p] = 0ull;

    const int NT = ED / BK2;
    for (int kt = 0; kt < NT; ++kt) {
        const int buf = kt & 1;
        const float* cb = ct + buf * (BK2 * NE);
        if (kt + 1 < NT && tid == 0) {
            u32 m = buf ? mb0 : mb1;
            mbar_expect_tx(m, C2BYTES);
            bulk_g2s(ct_u32 + (u32)((buf ^ 1) * C2BYTES),
                     g_cnT + (size_t)(kt + 1) * BK2 * NE, C2BYTES, m);
        }
        #pragma unroll
        for (int k = 0; k < BK2; ++k) {
            const int kk = kt * BK2 + k;
            ulonglong2 qa0 = *(const ulonglong2*)(Pd + kk * PDP + 2 * mb + 0);
            ulonglong2 qa1 = *(const ulonglong2*)(Pd + kk * PDP + 2 * mb + 4);
            ulonglong2 qa2 = *(const ulonglong2*)(Pd + kk * PDP + 2 * mb + 8);
            ulonglong2 qa3 = *(const ulonglong2*)(Pd + kk * PDP + 2 * mb + 12);
            ulonglong2 qb0 = *(const ulonglong2*)(cb + k * NE + nA);
            ulonglong2 qb1 = *(const ulonglong2*)(cb + k * NE + nB);
            u64 B0 = qb0.x, B1 = qb0.y, B2 = qb1.x, B3 = qb1.y;
            ffma2(acc[0][0], qa0.x, B0); ffma2(acc[0][1], qa0.x, B1);
            ffma2(acc[0][2], qa0.x, B2); ffma2(acc[0][3], qa0.x, B3);
            ffma2(acc[1][0], qa0.y, B0); ffma2(acc[1][1], qa0.y, B1);
            ffma2(acc[1][2], qa0.y, B2); ffma2(acc[1][3], qa0.y, B3);
            ffma2(acc[2][0], qa1.x, B0); ffma2(acc[2][1], qa1.x, B1);
            ffma2(acc[2][2], qa1.x, B2); ffma2(acc[2][3], qa1.x, B3);
            ffma2(acc[3][0], qa1.y, B0); ffma2(acc[3][1], qa1.y, B1);
            ffma2(acc[3][2], qa1.y, B2); ffma2(acc[3][3], qa1.y, B3);
            ffma2(acc[4][0], qa2.x, B0); ffma2(acc[4][1], qa2.x, B1);
            ffma2(acc[4][2], qa2.x, B2); ffma2(acc[4][3], qa2.x, B3);
            ffma2(acc[5][0], qa2.y, B0); ffma2(acc[5][1], qa2.y, B1);
            ffma2(acc[5][2], qa2.y, B2); ffma2(acc[5][3], qa2.y, B3);
            ffma2(acc[6][0], qa3.x, B0); ffma2(acc[6][1], qa3.x, B1);
            ffma2(acc[6][2], qa3.x, B2); ffma2(acc[6][3], qa3.x, B3);
            ffma2(acc[7][0], qa3.y, B0); ffma2(acc[7][1], qa3.y, B1);
            ffma2(acc[7][2], qa3.y, B2); ffma2(acc[7][3], qa3.y, B3);
        }
        if (kt + 1 < NT) {
            if (buf) { mbar_wait(mb0, ph0); ph0 ^= 1; }
            else     { mbar_wait(mb1, ph1); ph1 ^= 1; }
        }
        __syncthreads();
    }

    // per-thread top-2 over this thread's 8 experts x 8 tokens
    float v1[8], v2[8]; int i1[8], i2[8];
    #pragma unroll
    for (int r = 0; r < 8; ++r) { v1[r] = -INFINITY; v2[r] = -INFINITY; i1[r] = 0; i2[r] = 0; }
    #pragma unroll
    for (int m = 0; m < 8; ++m)
        #pragma unroll
        for (int np = 0; np < 4; ++np) {
            float lo, hi; unpack2(acc[m][np], lo, hi);
            int base = (np < 2) ? (nA + 2 * np) : (nB + 2 * (np - 2));
            upd(lo, base,     v1[m], i1[m], v2[m], i2[m]);
            upd(hi, base + 1, v1[m], i1[m], v2[m], i2[m]);
        }
    // warp butterfly: top-2 over the warp's 256-expert half per token
    #pragma unroll
    for (int r = 0; r < 8; ++r)
        #pragma unroll
        for (int o = 16; o; o >>= 1) {
            float o1 = __shfl_xor_sync(0xffffffffu, v1[r], o);
            int  oi1 = __shfl_xor_sync(0xffffffffu, i1[r], o);
            float o2 = __shfl_xor_sync(0xffffffffu, v2[r], o);
            int  oi2 = __shfl_xor_sync(0xffffffffu, i2[r], o);
            upd(o1, oi1, v1[r], i1[r], v2[r], i2[r]);
            upd(o2, oi2, v1[r], i1[r], v2[r], i2[r]);
        }

    // cross-half merge via smem (reuse ct region; all reads done after last sync)
    float4* mg = (float4*)ct;              // [TT][2]
    if (lane == 0) {
        #pragma unroll
        for (int r = 0; r < 8; ++r)
            mg[(mb + r) * 2 + (w & 1)] =
                make_float4(v1[r], __int_as_float(i1[r]), v2[r], __int_as_float(i2[r]));
    }
    __syncthreads();

    if (tid < TT) {
        float4 A = mg[tid * 2 + 0];
        float4 B = mg[tid * 2 + 1];
        float V1 = A.x, V2 = A.z;
        int I1 = __float_as_int(A.y), I2 = __float_as_int(A.w);
        upd(B.x, __float_as_int(B.y), V1, I1, V2, I2);
        upd(B.z, __float_as_int(B.w), V1, I1, V2, I2);
        int token = t0 + tid;
        float inv = 1.f / fmaxf(sqrtf(g_sq[token]), 1e-12f);
        float e2 = expf((V2 - V1) * inv);
        float den = 1.f + e2;
        out[2 * token]     = 1.f / den;
        out[2 * token + 1] = e2 / den;
        float* oi = out + 2 * (size_t)ntok;
        oi[2 * token]     = (float)I1;
        oi[2 * token + 1] = (float)I2;
    }
}

extern "C" void kernel_launch(void* const* d_in, const int* in_sizes, int n_in,
                              void* d_out, int out_size) {
    const float* x = (const float*)d_in[0];
    const float* W = (const float*)d_in[1];
    const float* b = (const float*)d_in[2];
    const float* c = (const float*)d_in[3];
    int ntok = in_sizes[0] / IN_DIM;   // 131072

    cnorm_kernel<<<NE, ED>>>(c);
    prep_wt_kernel<<<dim3(IN_DIM / 32, ED / 32), dim3(32, 8)>>>(W);

    int smem1 = (2 * BK1 * XDP + 2 * BK1 * ED) * (int)sizeof(float);   // 99328 B
    cudaFuncSetAttribute(k1_kernel, cudaFuncAttributeMaxDynamicSharedMemorySize, smem1);
    k1_kernel<<<ntok / 64, 256, smem1>>>(x, b);

    int smem2 = (ED * PDP + 2 * BK2 * NE) * (int)sizeof(float);        // 102400 B
    cudaFuncSetAttribute(k2_kernel, cudaFuncAttributeMaxDynamicSharedMemorySize, smem2);
    k2_kernel<<<ntok / TT, 256, smem2>>>((float*)d_out, ntok);
}